// round 2
// baseline (speedup 1.0000x reference)
#include <cuda_runtime.h>
#include <cuda_bf16.h>

// Problem constants (match reference)
#define NN 100000
#define CH 64
#define OC2 32

// Scratch (device globals, no allocation allowed)
__device__ float g_agg[NN * CH];   // aggregation buffer (reused both layers)
__device__ float g_cnt[NN];        // in-degree counts
__device__ float g_h1[NN * CH];    // layer-1 output

// ---------------------------------------------------------------------------
// Zero a float buffer
__global__ void zero_kernel(float* __restrict__ p, int n) {
    int i = blockIdx.x * blockDim.x + threadIdx.x;
    int stride = gridDim.x * blockDim.x;
    for (; i < n; i += stride) p[i] = 0.0f;
}

// ---------------------------------------------------------------------------
// Edge scatter: 16 threads per edge, each handles 4 channels via float4 load
// + 4 atomicAdds. Optionally also counts in-degree (first layer only).
__global__ void scatter_kernel(const float* __restrict__ feat,
                               const int* __restrict__ src,
                               const int* __restrict__ dst,
                               float* __restrict__ agg,
                               float* __restrict__ cnt,
                               int E, int do_count) {
    long long t = (long long)blockIdx.x * blockDim.x + threadIdx.x;
    int e = (int)(t >> 4);
    int c = ((int)t & 15) << 2;
    if (e >= E) return;
    int s = __ldg(&src[e]);
    int d = __ldg(&dst[e]);
    float4 v = *reinterpret_cast<const float4*>(feat + (long long)s * CH + c);
    float* p = agg + (long long)d * CH + c;
    atomicAdd(p + 0, v.x);
    atomicAdd(p + 1, v.y);
    atomicAdd(p + 2, v.z);
    atomicAdd(p + 3, v.w);
    if (do_count && c == 0) atomicAdd(&cnt[d], 1.0f);
}

// ---------------------------------------------------------------------------
// SAGE node update: out[n,:] = (agg[n,:]/max(cnt,1)) @ Wl + hin[n,:] @ Wr + b
// W layout: [64, OC] row-major (fan_in major), so W[k*OC + j].
// One node per thread; weights in shared memory; float4 weight loads.
template <int OC, bool RELU>
__global__ __launch_bounds__(128)
void sage_kernel(const float* __restrict__ agg, const float* __restrict__ cnt,
                 const float* __restrict__ hin,
                 const float* __restrict__ Wl, const float* __restrict__ Wr,
                 const float* __restrict__ bias, float* __restrict__ out, int N) {
    __shared__ float sWl[CH * OC];
    __shared__ float sWr[CH * OC];
    __shared__ float sb[OC];
    for (int i = threadIdx.x; i < CH * OC; i += blockDim.x) {
        sWl[i] = Wl[i];
        sWr[i] = Wr[i];
    }
    for (int i = threadIdx.x; i < OC; i += blockDim.x) sb[i] = bias[i];
    __syncthreads();

    int n = blockIdx.x * blockDim.x + threadIdx.x;
    if (n >= N) return;

    float acc[OC];
#pragma unroll
    for (int j = 0; j < OC; j++) acc[j] = sb[j];

    float inv = 1.0f / fmaxf(__ldg(&cnt[n]), 1.0f);

    const float4* sWl4 = reinterpret_cast<const float4*>(sWl);
    const float4* sWr4 = reinterpret_cast<const float4*>(sWr);
    const float* arow = agg + (long long)n * CH;
    const float* hrow = hin + (long long)n * CH;

#pragma unroll 4
    for (int k = 0; k < CH; k++) {
        float a = arow[k] * inv;
#pragma unroll
        for (int j4 = 0; j4 < OC / 4; j4++) {
            float4 w = sWl4[k * (OC / 4) + j4];
            acc[j4 * 4 + 0] = fmaf(a, w.x, acc[j4 * 4 + 0]);
            acc[j4 * 4 + 1] = fmaf(a, w.y, acc[j4 * 4 + 1]);
            acc[j4 * 4 + 2] = fmaf(a, w.z, acc[j4 * 4 + 2]);
            acc[j4 * 4 + 3] = fmaf(a, w.w, acc[j4 * 4 + 3]);
        }
    }
#pragma unroll 4
    for (int k = 0; k < CH; k++) {
        float a = hrow[k];
#pragma unroll
        for (int j4 = 0; j4 < OC / 4; j4++) {
            float4 w = sWr4[k * (OC / 4) + j4];
            acc[j4 * 4 + 0] = fmaf(a, w.x, acc[j4 * 4 + 0]);
            acc[j4 * 4 + 1] = fmaf(a, w.y, acc[j4 * 4 + 1]);
            acc[j4 * 4 + 2] = fmaf(a, w.z, acc[j4 * 4 + 2]);
            acc[j4 * 4 + 3] = fmaf(a, w.w, acc[j4 * 4 + 3]);
        }
    }

    float4* orow = reinterpret_cast<float4*>(out + (long long)n * OC);
#pragma unroll
    for (int j4 = 0; j4 < OC / 4; j4++) {
        float4 v;
        v.x = acc[j4 * 4 + 0];
        v.y = acc[j4 * 4 + 1];
        v.z = acc[j4 * 4 + 2];
        v.w = acc[j4 * 4 + 3];
        if (RELU) {
            v.x = fmaxf(v.x, 0.0f);
            v.y = fmaxf(v.y, 0.0f);
            v.z = fmaxf(v.z, 0.0f);
            v.w = fmaxf(v.w, 0.0f);
        }
        orow[j4] = v;
    }
}

// ---------------------------------------------------------------------------
extern "C" void kernel_launch(void* const* d_in, const int* in_sizes, int n_in,
                              void* d_out, int out_size) {
    const float* x = (const float*)d_in[0];
    const int* ei = (const int*)d_in[1];
    const float* W1_l = (const float*)d_in[2];
    const float* W1_r = (const float*)d_in[3];
    const float* b1 = (const float*)d_in[4];
    const float* W2_l = (const float*)d_in[5];
    const float* W2_r = (const float*)d_in[6];
    const float* b2 = (const float*)d_in[7];
    float* out = (float*)d_out;

    const int N = in_sizes[0] / CH;
    const int E = in_sizes[1] / 2;
    const int* src = ei;
    const int* dst = ei + E;

    float* agg;
    float* cnt;
    float* h1;
    cudaGetSymbolAddress((void**)&agg, g_agg);
    cudaGetSymbolAddress((void**)&cnt, g_cnt);
    cudaGetSymbolAddress((void**)&h1, g_h1);

    const int ZB = 256;
    // Layer 1: zero agg + cnt, scatter x (+count), node update -> h1 (relu)
    zero_kernel<<<2048, ZB>>>(agg, N * CH);
    zero_kernel<<<256, ZB>>>(cnt, N);
    {
        long long threads = (long long)E * 16;
        int blocks = (int)((threads + 255) / 256);
        scatter_kernel<<<blocks, 256>>>(x, src, dst, agg, cnt, E, 1);
    }
    sage_kernel<CH, true><<<(N + 127) / 128, 128>>>(agg, cnt, x, W1_l, W1_r, b1, h1, N);

    // Layer 2: zero agg, scatter h1, node update -> out
    zero_kernel<<<2048, ZB>>>(agg, N * CH);
    {
        long long threads = (long long)E * 16;
        int blocks = (int)((threads + 255) / 256);
        scatter_kernel<<<blocks, 256>>>(h1, src, dst, agg, cnt, E, 0);
    }
    sage_kernel<OC2, false><<<(N + 127) / 128, 128>>>(agg, cnt, h1, W2_l, W2_r, b2, out, N);
}

// round 5
// speedup vs baseline: 1.8086x; 1.8086x over previous
#include <cuda_runtime.h>
#include <cuda_bf16.h>

#define NN 100000
#define NE 1200000
#define CH 64
#define OC2 32

// Scratch (device globals — no allocation allowed)
__device__ int   g_deg[NN];
__device__ int   g_off[NN];
__device__ int   g_pos[NN];
__device__ int   g_adj[NE];
__device__ int   g_bsum[128];
__device__ float g_h1[NN * CH];

// ---------------------------------------------------------------------------
__global__ void zero_deg_kernel(int* __restrict__ deg, int n) {
    int i = blockIdx.x * blockDim.x + threadIdx.x;
    if (i < n) deg[i] = 0;
}

__global__ void hist_kernel(const int* __restrict__ dst, int* __restrict__ deg, int E) {
    int e = blockIdx.x * blockDim.x + threadIdx.x;
    if (e < E) atomicAdd(&deg[dst[e]], 1);
}

// Chunk = 1024 elements, block = 256 threads, thread handles 4 contiguous.
__global__ void scanA_kernel(const int* __restrict__ deg, int* __restrict__ bsum, int N) {
    __shared__ int sh[256];
    int b = blockIdx.x, t = threadIdx.x;
    int base = b * 1024 + t * 4;
    int s = 0;
#pragma unroll
    for (int u = 0; u < 4; u++) {
        int i = base + u;
        if (i < N) s += deg[i];
    }
    sh[t] = s;
    __syncthreads();
    // reduce
    for (int d = 128; d > 0; d >>= 1) {
        if (t < d) sh[t] += sh[t + d];
        __syncthreads();
    }
    if (t == 0) bsum[b] = sh[0];
}

__global__ void scanB_kernel(int* __restrict__ bsum, int nchunks) {
    if (threadIdx.x == 0 && blockIdx.x == 0) {
        int run = 0;
        for (int i = 0; i < nchunks; i++) {
            int v = bsum[i];
            bsum[i] = run;
            run += v;
        }
    }
}

__global__ void scanC_kernel(const int* __restrict__ deg, const int* __restrict__ bsum,
                             int* __restrict__ off, int* __restrict__ pos, int N) {
    __shared__ int sh[256];
    int b = blockIdx.x, t = threadIdx.x;
    int base = b * 1024 + t * 4;
    int v[4];
    int s = 0;
#pragma unroll
    for (int u = 0; u < 4; u++) {
        int i = base + u;
        v[u] = (i < N) ? deg[i] : 0;
        s += v[u];
    }
    sh[t] = s;
    __syncthreads();
    // inclusive Hillis-Steele scan
    for (int d = 1; d < 256; d <<= 1) {
        int add = (t >= d) ? sh[t - d] : 0;
        __syncthreads();
        sh[t] += add;
        __syncthreads();
    }
    int run = bsum[b] + sh[t] - s;  // exclusive prefix for this thread
#pragma unroll
    for (int u = 0; u < 4; u++) {
        int i = base + u;
        if (i < N) {
            off[i] = run;
            pos[i] = run;
            run += v[u];
        }
    }
}

__global__ void fill_kernel(const int* __restrict__ src, const int* __restrict__ dst,
                            int* __restrict__ pos, int* __restrict__ adj, int E) {
    int e = blockIdx.x * blockDim.x + threadIdx.x;
    if (e < E) {
        int p = atomicAdd(&pos[dst[e]], 1);
        adj[p] = src[e];
    }
}

// ---------------------------------------------------------------------------
// Fused gather-aggregate + dual-GEMM SAGE layer.
//   Block = 64 nodes, 128 threads.
//   Stage 1: each warp gathers 16 nodes' mean-aggregated rows + own feature
//            row into k-major smem A-tile sAT[128][64] (row pitch 68 floats).
//   Stage 2: register-tiled GEMM: C[64 x OC] = A[64 x 128] @ W[128 x OC]+b.
//            Thread tile = NPT nodes x 4 channels; per-k: broadcast LDS.128
//            a-loads + one float4 w-load -> FMA-bound.
#define APITCH 68

template <int OC, bool RELU>
__global__ __launch_bounds__(128)
void sage_fused(const float* __restrict__ feat,
                const float* __restrict__ Wl, const float* __restrict__ Wr,
                const float* __restrict__ bias, float* __restrict__ out,
                const int* __restrict__ deg, const int* __restrict__ off,
                const int* __restrict__ adj, int N) {
    extern __shared__ float smem[];
    float* sAT = smem;                   // [128][APITCH]
    float* sW  = smem + 128 * APITCH;    // [128][OC], rows 0..63 = Wl, 64..127 = Wr

    const int t = threadIdx.x;
    for (int i = t; i < 64 * OC; i += 128) {
        sW[i] = Wl[i];
        sW[64 * OC + i] = Wr[i];
    }

    const int base = blockIdx.x * 64;
    const int warp = t >> 5, lane = t & 31;
    const float2* feat2 = (const float2*)feat;

    // ---- Stage 1: gather ----
    for (int i = 0; i < 16; i++) {
        int ln = warp * 16 + i;
        int n = base + ln;
        float ax = 0.f, ay = 0.f, hx = 0.f, hy = 0.f;
        if (n < N) {
            int d0 = __ldg(&deg[n]);
            int o  = __ldg(&off[n]);
            float2 a0 = make_float2(0.f, 0.f);
            float2 a1 = make_float2(0.f, 0.f);
            int j = 0;
            for (; j + 1 < d0; j += 2) {
                int s0 = __ldg(&adj[o + j]);
                int s1 = __ldg(&adj[o + j + 1]);
                float2 v0 = __ldg(&feat2[s0 * 32 + lane]);
                float2 v1 = __ldg(&feat2[s1 * 32 + lane]);
                a0.x += v0.x; a0.y += v0.y;
                a1.x += v1.x; a1.y += v1.y;
            }
            if (j < d0) {
                int s0 = __ldg(&adj[o + j]);
                float2 v0 = __ldg(&feat2[s0 * 32 + lane]);
                a0.x += v0.x; a0.y += v0.y;
            }
            float inv = 1.0f / fmaxf((float)d0, 1.0f);
            ax = (a0.x + a1.x) * inv;
            ay = (a0.y + a1.y) * inv;
            float2 hv = __ldg(&feat2[n * 32 + lane]);
            hx = hv.x; hy = hv.y;
        }
        sAT[(2 * lane) * APITCH + ln]       = ax;
        sAT[(2 * lane + 1) * APITCH + ln]   = ay;
        sAT[(64 + 2 * lane) * APITCH + ln]  = hx;
        sAT[(65 + 2 * lane) * APITCH + ln]  = hy;
    }
    __syncthreads();

    // ---- Stage 2: GEMM ----
    constexpr int TX = OC / 4;      // channel groups of 4
    constexpr int TY = 128 / TX;    // node groups
    constexpr int NPT = 64 / TY;    // nodes per thread
    constexpr int NQ = NPT / 4;     // float4 a-loads per k
    const int tx = t % TX, ty = t / TX;

    float acc[NPT][4];
    float4 bv = __ldg(((const float4*)bias) + tx);
#pragma unroll
    for (int i = 0; i < NPT; i++) {
        acc[i][0] = bv.x; acc[i][1] = bv.y; acc[i][2] = bv.z; acc[i][3] = bv.w;
    }

    const float4* sAT4 = (const float4*)sAT;  // row pitch APITCH/4 = 17
    const float4* sW4  = (const float4*)sW;   // row pitch TX

#pragma unroll 4
    for (int k = 0; k < 128; k++) {
        float4 w = sW4[k * TX + tx];
        float4 areg[NQ];
#pragma unroll
        for (int q = 0; q < NQ; q++) areg[q] = sAT4[k * (APITCH / 4) + ty * NQ + q];
        const float* af = (const float*)areg;
#pragma unroll
        for (int i = 0; i < NPT; i++) {
            float a = af[i];
            acc[i][0] = fmaf(a, w.x, acc[i][0]);
            acc[i][1] = fmaf(a, w.y, acc[i][1]);
            acc[i][2] = fmaf(a, w.z, acc[i][2]);
            acc[i][3] = fmaf(a, w.w, acc[i][3]);
        }
    }

#pragma unroll
    for (int i = 0; i < NPT; i++) {
        int n = base + ty * NPT + i;
        if (n < N) {
            float4 v;
            v.x = acc[i][0]; v.y = acc[i][1]; v.z = acc[i][2]; v.w = acc[i][3];
            if (RELU) {
                v.x = fmaxf(v.x, 0.f); v.y = fmaxf(v.y, 0.f);
                v.z = fmaxf(v.z, 0.f); v.w = fmaxf(v.w, 0.f);
            }
            ((float4*)out)[n * (OC / 4) + tx] = v;
        }
    }
}

// ---------------------------------------------------------------------------
extern "C" void kernel_launch(void* const* d_in, const int* in_sizes, int n_in,
                              void* d_out, int out_size) {
    const float* x    = (const float*)d_in[0];
    const int*   ei   = (const int*)d_in[1];
    const float* W1_l = (const float*)d_in[2];
    const float* W1_r = (const float*)d_in[3];
    const float* b1   = (const float*)d_in[4];
    const float* W2_l = (const float*)d_in[5];
    const float* W2_r = (const float*)d_in[6];
    const float* b2   = (const float*)d_in[7];
    float* out = (float*)d_out;

    const int N = in_sizes[0] / CH;
    const int E = in_sizes[1] / 2;
    const int* src = ei;
    const int* dst = ei + E;

    int *deg, *off, *pos, *adj, *bsum;
    float* h1;
    cudaGetSymbolAddress((void**)&deg, g_deg);
    cudaGetSymbolAddress((void**)&off, g_off);
    cudaGetSymbolAddress((void**)&pos, g_pos);
    cudaGetSymbolAddress((void**)&adj, g_adj);
    cudaGetSymbolAddress((void**)&bsum, g_bsum);
    cudaGetSymbolAddress((void**)&h1, g_h1);

    const int nchunks = (N + 1023) / 1024;

    // ---- Build CSR ----
    zero_deg_kernel<<<(N + 255) / 256, 256>>>(deg, N);
    hist_kernel<<<(E + 255) / 256, 256>>>(dst, deg, E);
    scanA_kernel<<<nchunks, 256>>>(deg, bsum, N);
    scanB_kernel<<<1, 32>>>(bsum, nchunks);
    scanC_kernel<<<nchunks, 256>>>(deg, bsum, off, pos, N);
    fill_kernel<<<(E + 255) / 256, 256>>>(src, dst, pos, adj, E);

    // ---- Layers ----
    const int smem1 = 128 * APITCH * 4 + 128 * CH * 4;   // 67584
    const int smem2 = 128 * APITCH * 4 + 128 * OC2 * 4;  // 51200
    cudaFuncSetAttribute(sage_fused<CH, true>,
                         cudaFuncAttributeMaxDynamicSharedMemorySize, smem1);
    cudaFuncSetAttribute(sage_fused<OC2, false>,
                         cudaFuncAttributeMaxDynamicSharedMemorySize, smem2);

    int blocks = (N + 63) / 64;
    sage_fused<CH, true><<<blocks, 128, smem1>>>(x, W1_l, W1_r, b1, h1, deg, off, adj, N);
    sage_fused<OC2, false><<<blocks, 128, smem2>>>(h1, W2_l, W2_r, b2, out, deg, off, adj, N);
}

// round 7
// speedup vs baseline: 2.4567x; 1.3583x over previous
#include <cuda_runtime.h>
#include <cuda_bf16.h>

#define NN 100000
#define NE 1200000
#define CH 64
#define OC2 32

// Scratch (device globals — no allocation allowed)
__device__ int   g_deg[NN];
__device__ int   g_off[NN];
__device__ int   g_pos[NN];
__device__ int   g_adj[NE];
__device__ int   g_bsum[128];
__device__ float g_agg[NN * CH];
__device__ float g_h1[NN * CH];

// ---------------------------------------------------------------------------
__global__ void zero_deg_kernel(int* __restrict__ deg, int n) {
    int i = blockIdx.x * blockDim.x + threadIdx.x;
    if (i < n) deg[i] = 0;
}

__global__ void hist_kernel(const int* __restrict__ dst, int* __restrict__ deg, int E) {
    int e = blockIdx.x * blockDim.x + threadIdx.x;
    if (e < E) atomicAdd(&deg[dst[e]], 1);
}

// Chunk = 1024 elements, block = 256 threads, thread handles 4 contiguous.
__global__ void scanA_kernel(const int* __restrict__ deg, int* __restrict__ bsum, int N) {
    __shared__ int sh[256];
    int b = blockIdx.x, t = threadIdx.x;
    int base = b * 1024 + t * 4;
    int s = 0;
#pragma unroll
    for (int u = 0; u < 4; u++) {
        int i = base + u;
        if (i < N) s += deg[i];
    }
    sh[t] = s;
    __syncthreads();
    for (int d = 128; d > 0; d >>= 1) {
        if (t < d) sh[t] += sh[t + d];
        __syncthreads();
    }
    if (t == 0) bsum[b] = sh[0];
}

// Parallel exclusive scan over <=128 chunk sums (single block).
__global__ void scanB_kernel(int* __restrict__ bsum, int nchunks) {
    __shared__ int sh[128];
    int t = threadIdx.x;
    int v = (t < nchunks) ? bsum[t] : 0;
    sh[t] = v;
    __syncthreads();
    for (int d = 1; d < 128; d <<= 1) {
        int add = (t >= d) ? sh[t - d] : 0;
        __syncthreads();
        sh[t] += add;
        __syncthreads();
    }
    if (t < nchunks) bsum[t] = sh[t] - v;  // exclusive
}

__global__ void scanC_kernel(const int* __restrict__ deg, const int* __restrict__ bsum,
                             int* __restrict__ off, int* __restrict__ pos, int N) {
    __shared__ int sh[256];
    int b = blockIdx.x, t = threadIdx.x;
    int base = b * 1024 + t * 4;
    int v[4];
    int s = 0;
#pragma unroll
    for (int u = 0; u < 4; u++) {
        int i = base + u;
        v[u] = (i < N) ? deg[i] : 0;
        s += v[u];
    }
    sh[t] = s;
    __syncthreads();
    for (int d = 1; d < 256; d <<= 1) {
        int add = (t >= d) ? sh[t - d] : 0;
        __syncthreads();
        sh[t] += add;
        __syncthreads();
    }
    int run = bsum[b] + sh[t] - s;  // exclusive prefix for this thread
#pragma unroll
    for (int u = 0; u < 4; u++) {
        int i = base + u;
        if (i < N) {
            off[i] = run;
            pos[i] = run;
            run += v[u];
        }
    }
}

__global__ void fill_kernel(const int* __restrict__ src, const int* __restrict__ dst,
                            int* __restrict__ pos, int* __restrict__ adj, int E) {
    int e = blockIdx.x * blockDim.x + threadIdx.x;
    if (e < E) {
        int p = atomicAdd(&pos[dst[e]], 1);
        adj[p] = src[e];
    }
}

// ---------------------------------------------------------------------------
// Gather + mean aggregate: one warp per node, lane covers 2 channels (float2).
// Unroll-by-4 edge loop: 4 independent adj loads then 4 independent feature
// loads -> MLP ~4-8; no smem -> full occupancy -> L2-BW-bound.
__global__ __launch_bounds__(256)
void gather_kernel(const float* __restrict__ feat,
                   const int* __restrict__ deg, const int* __restrict__ off,
                   const int* __restrict__ adj, float* __restrict__ agg, int N) {
    int w = (blockIdx.x * blockDim.x + threadIdx.x) >> 5;
    int lane = threadIdx.x & 31;
    if (w >= N) return;
    int d0 = __ldg(&deg[w]);
    int o  = __ldg(&off[w]);
    const float2* f2 = (const float2*)feat;
    float2 a0 = make_float2(0.f, 0.f), a1 = make_float2(0.f, 0.f);
    float2 a2 = make_float2(0.f, 0.f), a3 = make_float2(0.f, 0.f);
    int j = 0;
    for (; j + 3 < d0; j += 4) {
        int s0 = __ldg(&adj[o + j]);
        int s1 = __ldg(&adj[o + j + 1]);
        int s2 = __ldg(&adj[o + j + 2]);
        int s3 = __ldg(&adj[o + j + 3]);
        float2 v0 = __ldg(&f2[s0 * 32 + lane]);
        float2 v1 = __ldg(&f2[s1 * 32 + lane]);
        float2 v2 = __ldg(&f2[s2 * 32 + lane]);
        float2 v3 = __ldg(&f2[s3 * 32 + lane]);
        a0.x += v0.x; a0.y += v0.y;
        a1.x += v1.x; a1.y += v1.y;
        a2.x += v2.x; a2.y += v2.y;
        a3.x += v3.x; a3.y += v3.y;
    }
    for (; j < d0; j++) {
        int s0 = __ldg(&adj[o + j]);
        float2 v0 = __ldg(&f2[s0 * 32 + lane]);
        a0.x += v0.x; a0.y += v0.y;
    }
    float inv = 1.0f / fmaxf((float)d0, 1.0f);
    float2 r;
    r.x = (a0.x + a1.x + a2.x + a3.x) * inv;
    r.y = (a0.y + a1.y + a2.y + a3.y) * inv;
    ((float2*)agg)[w * 32 + lane] = r;
}

// ---------------------------------------------------------------------------
// Dual-GEMM SAGE layer: C[64 x OC] = [agg|feat][64 x 128] @ [Wl;Wr][128 x OC]+b
// Block = 64 nodes, 128 threads. A staged k-major in smem; register tiled.
#define APITCH 68

template <int OC, bool RELU>
__global__ __launch_bounds__(128)
void sage_mm(const float* __restrict__ agg, const float* __restrict__ feat,
             const float* __restrict__ Wl, const float* __restrict__ Wr,
             const float* __restrict__ bias, float* __restrict__ out, int N) {
    extern __shared__ float smem[];
    float* sAT = smem;                   // [128][APITCH]
    float* sW  = smem + 128 * APITCH;    // [128][OC]: rows 0..63 = Wl, 64..127 = Wr

    const int t = threadIdx.x;
    for (int i = t; i < 64 * OC; i += 128) {
        sW[i] = Wl[i];
        sW[64 * OC + i] = Wr[i];
    }

    const int base = blockIdx.x * 64;
    const int warp = t >> 5, lane = t & 31;
    const float2* agg2  = (const float2*)agg;
    const float2* feat2 = (const float2*)feat;

    // Stage A-tile (k-major): rows 0..63 = agg channels, 64..127 = self channels
#pragma unroll
    for (int i = 0; i < 16; i++) {
        int ln = warp * 16 + i;
        int n = base + ln;
        float2 av = make_float2(0.f, 0.f), hv = make_float2(0.f, 0.f);
        if (n < N) {
            av = __ldg(&agg2[n * 32 + lane]);
            hv = __ldg(&feat2[n * 32 + lane]);
        }
        sAT[(2 * lane) * APITCH + ln]      = av.x;
        sAT[(2 * lane + 1) * APITCH + ln]  = av.y;
        sAT[(64 + 2 * lane) * APITCH + ln] = hv.x;
        sAT[(65 + 2 * lane) * APITCH + ln] = hv.y;
    }
    __syncthreads();

    constexpr int TX = OC / 4;      // channel groups of 4
    constexpr int TY = 128 / TX;    // node groups
    constexpr int NPT = 64 / TY;    // nodes per thread
    constexpr int NQ = NPT / 4;     // float4 a-loads per k
    const int tx = t % TX, ty = t / TX;

    float acc[NPT][4];
    float4 bv = __ldg(((const float4*)bias) + tx);
#pragma unroll
    for (int i = 0; i < NPT; i++) {
        acc[i][0] = bv.x; acc[i][1] = bv.y; acc[i][2] = bv.z; acc[i][3] = bv.w;
    }

    const float4* sAT4 = (const float4*)sAT;  // row pitch 17
    const float4* sW4  = (const float4*)sW;   // row pitch TX

#pragma unroll 4
    for (int k = 0; k < 128; k++) {
        float4 w = sW4[k * TX + tx];
        float4 areg[NQ];
#pragma unroll
        for (int q = 0; q < NQ; q++) areg[q] = sAT4[k * (APITCH / 4) + ty * NQ + q];
        const float* af = (const float*)areg;
#pragma unroll
        for (int i = 0; i < NPT; i++) {
            float a = af[i];
            acc[i][0] = fmaf(a, w.x, acc[i][0]);
            acc[i][1] = fmaf(a, w.y, acc[i][1]);
            acc[i][2] = fmaf(a, w.z, acc[i][2]);
            acc[i][3] = fmaf(a, w.w, acc[i][3]);
        }
    }

#pragma unroll
    for (int i = 0; i < NPT; i++) {
        int n = base + ty * NPT + i;
        if (n < N) {
            float4 v;
            v.x = acc[i][0]; v.y = acc[i][1]; v.z = acc[i][2]; v.w = acc[i][3];
            if (RELU) {
                v.x = fmaxf(v.x, 0.f); v.y = fmaxf(v.y, 0.f);
                v.z = fmaxf(v.z, 0.f); v.w = fmaxf(v.w, 0.f);
            }
            ((float4*)out)[n * (OC / 4) + tx] = v;
        }
    }
}

// ---------------------------------------------------------------------------
extern "C" void kernel_launch(void* const* d_in, const int* in_sizes, int n_in,
                              void* d_out, int out_size) {
    const float* x    = (const float*)d_in[0];
    const int*   ei   = (const int*)d_in[1];
    const float* W1_l = (const float*)d_in[2];
    const float* W1_r = (const float*)d_in[3];
    const float* b1   = (const float*)d_in[4];
    const float* W2_l = (const float*)d_in[5];
    const float* W2_r = (const float*)d_in[6];
    const float* b2   = (const float*)d_in[7];
    float* out = (float*)d_out;

    const int N = in_sizes[0] / CH;
    const int E = in_sizes[1] / 2;
    const int* src = ei;
    const int* dst = ei + E;

    int *deg, *off, *pos, *adj, *bsum;
    float *agg, *h1;
    cudaGetSymbolAddress((void**)&deg, g_deg);
    cudaGetSymbolAddress((void**)&off, g_off);
    cudaGetSymbolAddress((void**)&pos, g_pos);
    cudaGetSymbolAddress((void**)&adj, g_adj);
    cudaGetSymbolAddress((void**)&bsum, g_bsum);
    cudaGetSymbolAddress((void**)&agg, g_agg);
    cudaGetSymbolAddress((void**)&h1, g_h1);

    const int nchunks = (N + 1023) / 1024;

    // ---- Build CSR ----
    zero_deg_kernel<<<(N + 255) / 256, 256>>>(deg, N);
    hist_kernel<<<(E + 255) / 256, 256>>>(dst, deg, E);
    scanA_kernel<<<nchunks, 256>>>(deg, bsum, N);
    scanB_kernel<<<1, 128>>>(bsum, nchunks);
    scanC_kernel<<<nchunks, 256>>>(deg, bsum, off, pos, N);
    fill_kernel<<<(E + 255) / 256, 256>>>(src, dst, pos, adj, E);

    // ---- Layers ----
    const int smem1 = 128 * APITCH * 4 + 128 * CH * 4;   // 67584
    const int smem2 = 128 * APITCH * 4 + 128 * OC2 * 4;  // 51200
    cudaFuncSetAttribute(sage_mm<CH, true>,
                         cudaFuncAttributeMaxDynamicSharedMemorySize, smem1);
    cudaFuncSetAttribute(sage_mm<OC2, false>,
                         cudaFuncAttributeMaxDynamicSharedMemorySize, smem2);

    int gblocks = (N * 32 + 255) / 256;   // warp per node, 8 nodes/block
    int mblocks = (N + 63) / 64;

    gather_kernel<<<gblocks, 256>>>(x, deg, off, adj, agg, N);
    sage_mm<CH, true><<<mblocks, 128, smem1>>>(agg, x, W1_l, W1_r, b1, h1, N);
    gather_kernel<<<gblocks, 256>>>(h1, deg, off, adj, agg, N);
    sage_mm<OC2, false><<<mblocks, 128, smem2>>>(agg, h1, W2_l, W2_r, b2, out, N);
}

// round 10
// speedup vs baseline: 3.7752x; 1.5367x over previous
#include <cuda_runtime.h>
#include <cuda_fp16.h>
#include <cstdint>

#define NN 100000
#define NE 1200000
#define CH 64
#define OC2 32

typedef unsigned int u32;

// Scratch (device globals — no allocation allowed)
__device__ int    g_deg[NN];
__device__ int    g_off[NN];
__device__ int    g_pos[NN];
__device__ int    g_adj[NE];
__device__ int    g_bsum[128];
__device__ __half g_xh[NN * CH];
__device__ __half g_h1h[NN * CH];
__device__ __half g_aggh[NN * CH];
__device__ __half g_w1h[128 * 64];
__device__ __half g_w2h[128 * 32];

// ---------------------------------------------------------------------------
__global__ void zero_deg_kernel(int* __restrict__ deg, int n) {
    int i = blockIdx.x * blockDim.x + threadIdx.x;
    if (i < n) deg[i] = 0;
}

__global__ void hist_kernel(const int* __restrict__ dst, int* __restrict__ deg, int E) {
    int e = blockIdx.x * blockDim.x + threadIdx.x;
    if (e < E) atomicAdd(&deg[dst[e]], 1);
}

__global__ void scanA_kernel(const int* __restrict__ deg, int* __restrict__ bsum, int N) {
    __shared__ int sh[256];
    int b = blockIdx.x, t = threadIdx.x;
    int base = b * 1024 + t * 4;
    int s = 0;
#pragma unroll
    for (int u = 0; u < 4; u++) {
        int i = base + u;
        if (i < N) s += deg[i];
    }
    sh[t] = s;
    __syncthreads();
    for (int d = 128; d > 0; d >>= 1) {
        if (t < d) sh[t] += sh[t + d];
        __syncthreads();
    }
    if (t == 0) bsum[b] = sh[0];
}

__global__ void scanB_kernel(int* __restrict__ bsum, int nchunks) {
    __shared__ int sh[128];
    int t = threadIdx.x;
    int v = (t < nchunks) ? bsum[t] : 0;
    sh[t] = v;
    __syncthreads();
    for (int d = 1; d < 128; d <<= 1) {
        int add = (t >= d) ? sh[t - d] : 0;
        __syncthreads();
        sh[t] += add;
        __syncthreads();
    }
    if (t < nchunks) bsum[t] = sh[t] - v;
}

__global__ void scanC_kernel(const int* __restrict__ deg, const int* __restrict__ bsum,
                             int* __restrict__ off, int* __restrict__ pos, int N) {
    __shared__ int sh[256];
    int b = blockIdx.x, t = threadIdx.x;
    int base = b * 1024 + t * 4;
    int v[4];
    int s = 0;
#pragma unroll
    for (int u = 0; u < 4; u++) {
        int i = base + u;
        v[u] = (i < N) ? deg[i] : 0;
        s += v[u];
    }
    sh[t] = s;
    __syncthreads();
    for (int d = 1; d < 256; d <<= 1) {
        int add = (t >= d) ? sh[t - d] : 0;
        __syncthreads();
        sh[t] += add;
        __syncthreads();
    }
    int run = bsum[b] + sh[t] - s;
#pragma unroll
    for (int u = 0; u < 4; u++) {
        int i = base + u;
        if (i < N) {
            off[i] = run;
            pos[i] = run;
            run += v[u];
        }
    }
}

__global__ void fill_kernel(const int* __restrict__ src, const int* __restrict__ dst,
                            int* __restrict__ pos, int* __restrict__ adj, int E) {
    int e = blockIdx.x * blockDim.x + threadIdx.x;
    if (e < E) {
        int p = atomicAdd(&pos[dst[e]], 1);
        adj[p] = src[e];
    }
}

// ---------------------------------------------------------------------------
// fp32 -> fp16 conversions
__global__ void conv_x_kernel(const float2* __restrict__ x2, __half2* __restrict__ xh2, int n2) {
    int i = blockIdx.x * blockDim.x + threadIdx.x;
    if (i < n2) {
        float2 v = x2[i];
        xh2[i] = __floats2half2_rn(v.x, v.y);
    }
}

__global__ void conv_w_kernel(const float* __restrict__ W1l, const float* __restrict__ W1r,
                              const float* __restrict__ W2l, const float* __restrict__ W2r,
                              __half* __restrict__ w1h, __half* __restrict__ w2h) {
    int i = blockIdx.x * blockDim.x + threadIdx.x;
    if (i < 4096) w1h[i] = __float2half(W1l[i]);
    else if (i < 8192) w1h[i] = __float2half(W1r[i - 4096]);
    else if (i < 10240) w2h[i - 8192] = __float2half(W2l[i - 8192]);
    else if (i < 12288) w2h[i - 8192] = __float2half(W2r[i - 10240]);
}

// ---------------------------------------------------------------------------
// Gather + mean aggregate (fp16 features, fp32 accumulation, fp16 output).
// One warp per node, lane covers 2 channels (half2).
__global__ __launch_bounds__(256)
void gather_h_kernel(const __half2* __restrict__ f2,
                     const int* __restrict__ deg, const int* __restrict__ off,
                     const int* __restrict__ adj, __half2* __restrict__ aggh, int N) {
    int w = (blockIdx.x * blockDim.x + threadIdx.x) >> 5;
    int lane = threadIdx.x & 31;
    if (w >= N) return;
    int d0 = __ldg(&deg[w]);
    int o  = __ldg(&off[w]);
    float2 a0 = make_float2(0.f, 0.f), a1 = make_float2(0.f, 0.f);
    float2 a2 = make_float2(0.f, 0.f), a3 = make_float2(0.f, 0.f);
    int j = 0;
    for (; j + 3 < d0; j += 4) {
        int s0 = __ldg(&adj[o + j]);
        int s1 = __ldg(&adj[o + j + 1]);
        int s2 = __ldg(&adj[o + j + 2]);
        int s3 = __ldg(&adj[o + j + 3]);
        float2 v0 = __half22float2(__ldg(&f2[s0 * 32 + lane]));
        float2 v1 = __half22float2(__ldg(&f2[s1 * 32 + lane]));
        float2 v2 = __half22float2(__ldg(&f2[s2 * 32 + lane]));
        float2 v3 = __half22float2(__ldg(&f2[s3 * 32 + lane]));
        a0.x += v0.x; a0.y += v0.y;
        a1.x += v1.x; a1.y += v1.y;
        a2.x += v2.x; a2.y += v2.y;
        a3.x += v3.x; a3.y += v3.y;
    }
    for (; j < d0; j++) {
        int s0 = __ldg(&adj[o + j]);
        float2 v0 = __half22float2(__ldg(&f2[s0 * 32 + lane]));
        a0.x += v0.x; a0.y += v0.y;
    }
    float inv = 1.0f / fmaxf((float)d0, 1.0f);
    aggh[w * 32 + lane] =
        __floats2half2_rn((a0.x + a1.x + a2.x + a3.x) * inv,
                          (a0.y + a1.y + a2.y + a3.y) * inv);
}

// ---------------------------------------------------------------------------
// Tensor-core SAGE layer: C[64 x OC] = A[64 x 128] @ W[128 x OC] + b
//   A row n = [agg(n) fp16 (64) | feat(n) fp16 (64)], W = [Wl ; Wr] fp16.
//   Block = 64 nodes, 4 warps; warp handles one 16-row m-tile.
//   mma.sync.m16n8k16.f32.f16.f16.f32 with ldmatrix from swizzled smem.
template <int OC, bool RELU, bool OUTH>
__global__ __launch_bounds__(128)
void sage_mma(const __half* __restrict__ aggh, const __half* __restrict__ feath,
              const __half* __restrict__ Wh, const float* __restrict__ bias,
              void* __restrict__ outp, int N) {
    __shared__ __align__(16) __half sA[64 * 128];   // pitch 16 chunks of 16B, swizzled
    __shared__ __align__(16) __half sB[128 * 64];   // pitch 8 chunks of 16B, swizzled

    const int t = threadIdx.x, lane = t & 31, warp = t >> 5;
    const int base = blockIdx.x * 64;

    // Stage A: 64 rows x 16 chunks of 16B (chunks 0-7 = agg, 8-15 = self)
    const uint4* ag4 = (const uint4*)aggh;
    const uint4* ft4 = (const uint4*)feath;
#pragma unroll
    for (int i = t; i < 1024; i += 128) {
        int r = i >> 4, c = i & 15;
        int n = base + r;
        uint4 v = make_uint4(0u, 0u, 0u, 0u);
        if (n < N) v = (c < 8) ? __ldg(&ag4[n * 8 + c]) : __ldg(&ft4[n * 8 + c - 8]);
        int phys = (c & 8) | ((c & 7) ^ (r & 7));
        ((uint4*)sA)[r * 16 + phys] = v;
    }
    // Stage B: 128 rows x (OC/8) chunks, stored at pitch 8 chunks
    constexpr int BC = OC / 8;
    const uint4* w4 = (const uint4*)Wh;
#pragma unroll
    for (int i = t; i < 128 * BC; i += 128) {
        int r = i / BC, c = i % BC;
        ((uint4*)sB)[r * 8 + (c ^ (r & 7))] = __ldg(&w4[i]);
    }
    __syncthreads();

    constexpr int NT = OC / 8;
    float acc[NT][4];
#pragma unroll
    for (int nt = 0; nt < NT; nt++) {
        float2 bv = __ldg(((const float2*)bias) + nt * 4 + (lane & 3));
        acc[nt][0] = bv.x; acc[nt][1] = bv.y;
        acc[nt][2] = bv.x; acc[nt][3] = bv.y;
    }

    const int ra = warp * 16 + (lane & 15);
#pragma unroll
    for (int k2 = 0; k2 < 8; k2++) {
        int ca = k2 * 2 + (lane >> 4);
        u32 aaddr = (u32)__cvta_generic_to_shared(
            &((uint4*)sA)[ra * 16 + ((ca & 8) | ((ca & 7) ^ (ra & 7)))]);
        u32 a0, a1, a2, a3;
        asm volatile("ldmatrix.sync.aligned.m8n8.x4.shared.b16 {%0,%1,%2,%3}, [%4];"
                     : "=r"(a0), "=r"(a1), "=r"(a2), "=r"(a3) : "r"(aaddr));
        int rb = k2 * 16 + (lane & 15);
#pragma unroll
        for (int nt = 0; nt < NT; nt++) {
            u32 baddr = (u32)__cvta_generic_to_shared(
                &((uint4*)sB)[rb * 8 + (nt ^ (rb & 7))]);
            u32 b0, b1;
            asm volatile("ldmatrix.sync.aligned.m8n8.x2.trans.shared.b16 {%0,%1}, [%2];"
                         : "=r"(b0), "=r"(b1) : "r"(baddr));
            asm volatile(
                "mma.sync.aligned.m16n8k16.row.col.f32.f16.f16.f32 "
                "{%0,%1,%2,%3}, {%4,%5,%6,%7}, {%8,%9}, {%0,%1,%2,%3};"
                : "+f"(acc[nt][0]), "+f"(acc[nt][1]), "+f"(acc[nt][2]), "+f"(acc[nt][3])
                : "r"(a0), "r"(a1), "r"(a2), "r"(a3), "r"(b0), "r"(b1));
        }
    }

    // Epilogue. C mapping: c0,c1 -> row lane/4, cols 2*(lane%4)+{0,1}; c2,c3 -> row+8.
    int r0 = base + warp * 16 + (lane >> 2);
#pragma unroll
    for (int nt = 0; nt < NT; nt++) {
        float v0 = acc[nt][0], v1 = acc[nt][1], v2 = acc[nt][2], v3 = acc[nt][3];
        if (RELU) {
            v0 = fmaxf(v0, 0.f); v1 = fmaxf(v1, 0.f);
            v2 = fmaxf(v2, 0.f); v3 = fmaxf(v3, 0.f);
        }
        int cc = nt * 4 + (lane & 3);  // 2-element column group index
        if (OUTH) {
            __half2* o = (__half2*)outp;
            if (r0 < N) o[r0 * (OC / 2) + cc] = __floats2half2_rn(v0, v1);
            if (r0 + 8 < N) o[(r0 + 8) * (OC / 2) + cc] = __floats2half2_rn(v2, v3);
        } else {
            float2* o = (float2*)outp;
            if (r0 < N) o[r0 * (OC / 2) + cc] = make_float2(v0, v1);
            if (r0 + 8 < N) o[(r0 + 8) * (OC / 2) + cc] = make_float2(v2, v3);
        }
    }
}

// ---------------------------------------------------------------------------
extern "C" void kernel_launch(void* const* d_in, const int* in_sizes, int n_in,
                              void* d_out, int out_size) {
    const float* x    = (const float*)d_in[0];
    const int*   ei   = (const int*)d_in[1];
    const float* W1_l = (const float*)d_in[2];
    const float* W1_r = (const float*)d_in[3];
    const float* b1   = (const float*)d_in[4];
    const float* W2_l = (const float*)d_in[5];
    const float* W2_r = (const float*)d_in[6];
    const float* b2   = (const float*)d_in[7];
    float* out = (float*)d_out;

    const int N = in_sizes[0] / CH;
    const int E = in_sizes[1] / 2;
    const int* src = ei;
    const int* dst = ei + E;

    int *deg, *off, *pos, *adj, *bsum;
    __half *xh, *h1h, *aggh, *w1h, *w2h;
    cudaGetSymbolAddress((void**)&deg, g_deg);
    cudaGetSymbolAddress((void**)&off, g_off);
    cudaGetSymbolAddress((void**)&pos, g_pos);
    cudaGetSymbolAddress((void**)&adj, g_adj);
    cudaGetSymbolAddress((void**)&bsum, g_bsum);
    cudaGetSymbolAddress((void**)&xh, g_xh);
    cudaGetSymbolAddress((void**)&h1h, g_h1h);
    cudaGetSymbolAddress((void**)&aggh, g_aggh);
    cudaGetSymbolAddress((void**)&w1h, g_w1h);
    cudaGetSymbolAddress((void**)&w2h, g_w2h);

    const int nchunks = (N + 1023) / 1024;

    // ---- Build CSR ----
    zero_deg_kernel<<<(N + 255) / 256, 256>>>(deg, N);
    hist_kernel<<<(E + 255) / 256, 256>>>(dst, deg, E);
    scanA_kernel<<<nchunks, 256>>>(deg, bsum, N);
    scanB_kernel<<<1, 128>>>(bsum, nchunks);
    scanC_kernel<<<nchunks, 256>>>(deg, bsum, off, pos, N);
    fill_kernel<<<(E + 255) / 256, 256>>>(src, dst, pos, adj, E);

    // ---- Conversions ----
    conv_x_kernel<<<(N * 32 + 255) / 256, 256>>>((const float2*)x, (__half2*)xh, N * 32);
    conv_w_kernel<<<48, 256>>>(W1_l, W1_r, W2_l, W2_r, w1h, w2h);

    // ---- Layers ----
    int gblocks = (N * 32 + 255) / 256;
    int mblocks = (N + 63) / 64;

    gather_h_kernel<<<gblocks, 256>>>((const __half2*)xh, deg, off, adj, (__half2*)aggh, N);
    sage_mma<CH, true, true><<<mblocks, 128>>>(aggh, xh, w1h, b1, h1h, N);
    gather_h_kernel<<<gblocks, 256>>>((const __half2*)h1h, deg, off, adj, (__half2*)aggh, N);
    sage_mma<OC2, false, false><<<mblocks, 128>>>(aggh, h1h, w2h, b2, out, N);
}